// round 1
// baseline (speedup 1.0000x reference)
#include <cuda_runtime.h>

// Problem constants
#define NB 2
#define NL 2048
#define NDM 1024
#define NH 16
#define ND 64
#define NM (NB*NL)   // 4096

// Scratch: 4 projection outputs in (b,h,l,d) layout + attended output in (b*l, h*d) layout
__device__ float g_proj[4][(size_t)NB*NH*NL*ND];   // 4 x 16.8 MB
__device__ float g_att[(size_t)NB*NL*NDM];         // 16.8 MB

// ---------------------------------------------------------------------------
// Projection GEMM: Y[mat] = X @ W[mat]; output scattered to (b,h,l,d) layout.
// 128x64 block tile, BK=16, 256 threads, 8x4 register tile per thread.
// ---------------------------------------------------------------------------
__global__ __launch_bounds__(256) void proj_gemm(
    const float* __restrict__ X,
    const float* __restrict__ W0, const float* __restrict__ W1,
    const float* __restrict__ W2, const float* __restrict__ W3)
{
    __shared__ float As[16][132];   // A tile transposed [k][m], padded
    __shared__ float Bs[16][64];    // B tile [k][n]

    const float* W = (blockIdx.z==0)?W0:(blockIdx.z==1)?W1:(blockIdx.z==2)?W2:W3;
    float* Y = g_proj[blockIdx.z];

    const int m0 = blockIdx.y * 128;
    const int h  = blockIdx.x;        // each 64-wide N tile == one head
    const int n0 = h * 64;
    const int t  = threadIdx.x;
    const int ty = t >> 4, tx = t & 15;

    float acc[8][4];
#pragma unroll
    for (int i = 0; i < 8; i++) { acc[i][0]=0.f; acc[i][1]=0.f; acc[i][2]=0.f; acc[i][3]=0.f; }

    for (int k0 = 0; k0 < NDM; k0 += 16) {
        // Load A tile 128x16 (2 float4 per thread), store transposed
#pragma unroll
        for (int i = 0; i < 2; i++) {
            int idx = t + i*256;
            int row = idx >> 2, c4 = (idx & 3) << 2;
            float4 v = *(const float4*)(X + (size_t)(m0+row)*NDM + k0 + c4);
            As[c4+0][row]=v.x; As[c4+1][row]=v.y; As[c4+2][row]=v.z; As[c4+3][row]=v.w;
        }
        // Load B tile 16x64 (1 float4 per thread)
        {
            int row = t >> 4, c4 = (t & 15) << 2;
            *(float4*)&Bs[row][c4] = *(const float4*)(W + (size_t)(k0+row)*NDM + n0 + c4);
        }
        __syncthreads();

#pragma unroll
        for (int kk = 0; kk < 16; kk++) {
            float b0 = Bs[kk][tx*4+0], b1 = Bs[kk][tx*4+1];
            float b2 = Bs[kk][tx*4+2], b3 = Bs[kk][tx*4+3];
#pragma unroll
            for (int i = 0; i < 8; i++) {
                float a = As[kk][ty*8+i];
                acc[i][0] += a*b0; acc[i][1] += a*b1;
                acc[i][2] += a*b2; acc[i][3] += a*b3;
            }
        }
        __syncthreads();
    }

    // Epilogue: scatter to (b,h,l,d)
#pragma unroll
    for (int i = 0; i < 8; i++) {
        int m = m0 + ty*8 + i;
        int b = m >> 11;             // m / 2048
        int l = m & (NL-1);
        float4 v = make_float4(acc[i][0],acc[i][1],acc[i][2],acc[i][3]);
        *(float4*)(Y + (((size_t)(b*NH + h))*NL + l)*ND + tx*4) = v;
    }
}

// ---------------------------------------------------------------------------
// Flash attention over relational keys + Hadamard with relational queries.
// One block = (bh, 64-query tile). 256 threads: 4 threads per query row.
// Online softmax; O accumulates attn @ kr; epilogue multiplies by qr.
// ---------------------------------------------------------------------------
// Skewed row offset for the K tile (breaks the 4-way stride-16 row conflict)
__device__ __forceinline__ int krow_off(int c) { return c*68 + ((c >> 4) << 3); }

__global__ __launch_bounds__(256) void flash_kernel()
{
    extern __shared__ float sm[];
    float* qs  = sm;                 // [r*68 + d]          (4352 floats)
    float* ks  = sm + 4352;          // skewed rows         (4384 floats)
    float* krs = sm + 4352 + 4384;   // [c*68 + d]          (4352 floats)
    float* Ps  = krs + 4352;         // [r*68 + c]          (4352 floats)

    const int qt = blockIdx.x;       // query tile 0..31
    const int bh = blockIdx.y;       // b*H + h, 0..31
    const float* qp  = g_proj[0] + (size_t)bh*NL*ND;
    const float* kp  = g_proj[1] + (size_t)bh*NL*ND;
    const float* qrp = g_proj[2] + (size_t)bh*NL*ND;
    const float* krp = g_proj[3] + (size_t)bh*NL*ND;

    const int t = threadIdx.x;
    const int r = t >> 2;            // query row within tile (0..63)
    const int lane4 = t & 3;
    const int dcol  = lane4 * 16;    // 16-col slice of S owned by this thread

    // Load q tile (64x64): each thread loads 16 floats of its row
#pragma unroll
    for (int i = 0; i < 4; i++) {
        *(float4*)&qs[r*68 + dcol + i*4] =
            *(const float4*)(qp + (size_t)(qt*64 + r)*ND + dcol + i*4);
    }

    float O[16];
#pragma unroll
    for (int i = 0; i < 16; i++) O[i] = 0.f;
    float mrow = -1e30f, lsum = 0.f;

    const int qi = qt*64 + r;
    __syncthreads();

    for (int j = 0; j <= qt; j++) {
        // Load k and kr tiles (64x64 each)
#pragma unroll
        for (int i = 0; i < 4; i++) {
            *(float4*)&ks [krow_off(r) + dcol + i*4] =
                *(const float4*)(kp  + (size_t)(j*64 + r)*ND + dcol + i*4);
            *(float4*)&krs[r*68      + dcol + i*4] =
                *(const float4*)(krp + (size_t)(j*64 + r)*ND + dcol + i*4);
        }
        __syncthreads();

        // S[r][dcol+cc] = q[r] . k[dcol+cc]
        float s[16];
#pragma unroll
        for (int cc = 0; cc < 16; cc++) s[cc] = 0.f;
#pragma unroll
        for (int k4 = 0; k4 < 16; k4++) {
            float4 qv = *(float4*)&qs[r*68 + k4*4];
#pragma unroll
            for (int cc = 0; cc < 16; cc++) {
                float4 kv = *(float4*)&ks[krow_off(dcol+cc) + k4*4];
                s[cc] += qv.x*kv.x + qv.y*kv.y + qv.z*kv.z + qv.w*kv.w;
            }
        }
        // scale + causal mask
#pragma unroll
        for (int cc = 0; cc < 16; cc++) {
            int kj = j*64 + dcol + cc;
            s[cc] = (kj <= qi) ? s[cc]*0.125f : -1e30f;
        }
        // row max (4-lane butterfly within warp)
        float mx = s[0];
#pragma unroll
        for (int cc = 1; cc < 16; cc++) mx = fmaxf(mx, s[cc]);
        mx = fmaxf(mx, __shfl_xor_sync(0xffffffffu, mx, 1));
        mx = fmaxf(mx, __shfl_xor_sync(0xffffffffu, mx, 2));
        float m_new = fmaxf(mrow, mx);
        float corr  = __expf(mrow - m_new);

        float p[16], psum = 0.f;
#pragma unroll
        for (int cc = 0; cc < 16; cc++) { p[cc] = __expf(s[cc] - m_new); psum += p[cc]; }
        psum += __shfl_xor_sync(0xffffffffu, psum, 1);
        psum += __shfl_xor_sync(0xffffffffu, psum, 2);
        lsum = lsum*corr + psum;
        mrow = m_new;
#pragma unroll
        for (int i = 0; i < 16; i++) O[i] *= corr;

        // publish p to the row's other 3 lanes
#pragma unroll
        for (int i = 0; i < 4; i++)
            *(float4*)&Ps[r*68 + dcol + i*4] =
                make_float4(p[i*4+0], p[i*4+1], p[i*4+2], p[i*4+3]);
        __syncwarp();

        // O[d] += sum_c p[c]*kr[c][d]; this thread owns d = lane4*4 + i*16 + jj
#pragma unroll 16
        for (int c = 0; c < 64; c++) {
            float pc = Ps[r*68 + c];
#pragma unroll
            for (int i = 0; i < 4; i++) {
                float4 kv = *(float4*)&krs[c*68 + lane4*4 + i*16];
                O[i*4+0] += pc*kv.x; O[i*4+1] += pc*kv.y;
                O[i*4+2] += pc*kv.z; O[i*4+3] += pc*kv.w;
            }
        }
        __syncthreads();
    }

    // Epilogue: normalize, Hadamard with qr, write to (b*L+l, h*64+d)
    float inv = 1.f / lsum;
    int b = bh >> 4, h = bh & 15;
    int li = qt*64 + r;
    const float* qr_row = qrp + (size_t)li*ND;
    float* outp = g_att + ((size_t)(b*NL + li))*NDM + h*64;
#pragma unroll
    for (int i = 0; i < 4; i++) {
        int d = lane4*4 + i*16;
        float4 q4 = *(const float4*)(qr_row + d);
        float4 o;
        o.x = O[i*4+0]*inv*q4.x; o.y = O[i*4+1]*inv*q4.y;
        o.z = O[i*4+2]*inv*q4.z; o.w = O[i*4+3]*inv*q4.w;
        *(float4*)(outp + d) = o;
    }
}

// ---------------------------------------------------------------------------
// Output GEMM: out = g_att (4096x1024) @ wo (1024x1024)
// ---------------------------------------------------------------------------
__global__ __launch_bounds__(256) void out_gemm(const float* __restrict__ Wo,
                                                float* __restrict__ C)
{
    __shared__ float As[16][132];
    __shared__ float Bs[16][64];

    const float* A = g_att;
    const int m0 = blockIdx.y * 128;
    const int n0 = blockIdx.x * 64;
    const int t  = threadIdx.x;
    const int ty = t >> 4, tx = t & 15;

    float acc[8][4];
#pragma unroll
    for (int i = 0; i < 8; i++) { acc[i][0]=0.f; acc[i][1]=0.f; acc[i][2]=0.f; acc[i][3]=0.f; }

    for (int k0 = 0; k0 < NDM; k0 += 16) {
#pragma unroll
        for (int i = 0; i < 2; i++) {
            int idx = t + i*256;
            int row = idx >> 2, c4 = (idx & 3) << 2;
            float4 v = *(const float4*)(A + (size_t)(m0+row)*NDM + k0 + c4);
            As[c4+0][row]=v.x; As[c4+1][row]=v.y; As[c4+2][row]=v.z; As[c4+3][row]=v.w;
        }
        {
            int row = t >> 4, c4 = (t & 15) << 2;
            *(float4*)&Bs[row][c4] = *(const float4*)(Wo + (size_t)(k0+row)*NDM + n0 + c4);
        }
        __syncthreads();
#pragma unroll
        for (int kk = 0; kk < 16; kk++) {
            float b0 = Bs[kk][tx*4+0], b1 = Bs[kk][tx*4+1];
            float b2 = Bs[kk][tx*4+2], b3 = Bs[kk][tx*4+3];
#pragma unroll
            for (int i = 0; i < 8; i++) {
                float a = As[kk][ty*8+i];
                acc[i][0] += a*b0; acc[i][1] += a*b1;
                acc[i][2] += a*b2; acc[i][3] += a*b3;
            }
        }
        __syncthreads();
    }
#pragma unroll
    for (int i = 0; i < 8; i++) {
        int m = m0 + ty*8 + i;
        float4 v = make_float4(acc[i][0],acc[i][1],acc[i][2],acc[i][3]);
        *(float4*)(C + (size_t)m*NDM + n0 + tx*4) = v;
    }
}

// ---------------------------------------------------------------------------
extern "C" void kernel_launch(void* const* d_in, const int* in_sizes, int n_in,
                              void* d_out, int out_size)
{
    const float* x   = (const float*)d_in[0];
    const float* wq  = (const float*)d_in[1];
    const float* wk  = (const float*)d_in[2];
    const float* wqr = (const float*)d_in[3];
    const float* wkr = (const float*)d_in[4];
    const float* wo  = (const float*)d_in[5];
    float* out = (float*)d_out;

    // 1) projections (4 matrices)
    proj_gemm<<<dim3(NDM/64, NM/128, 4), 256>>>(x, wq, wk, wqr, wkr);

    // 2) flash attention + Hadamard
    const int smem_bytes = (4352 + 4384 + 4352 + 4352) * (int)sizeof(float); // 69760
    cudaFuncSetAttribute(flash_kernel, cudaFuncAttributeMaxDynamicSharedMemorySize, smem_bytes);
    flash_kernel<<<dim3(NL/64, NB*NH), 256, smem_bytes>>>();

    // 3) output projection
    out_gemm<<<dim3(NDM/64, NM/128), 256>>>(wo, out);
}

// round 3
// speedup vs baseline: 1.3541x; 1.3541x over previous
#include <cuda_runtime.h>
#include <cstdint>

// Problem constants
#define NB 2
#define NL 2048
#define NDM 1024
#define NH 16
#define ND 64
#define NM (NB*NL)   // 4096

// Scratch
__device__ float g_proj[4][(size_t)NB*NH*NL*ND];   // 4 x 16.8 MB (b,h,l,d)
__device__ float g_att[(size_t)NB*NL*NDM];         // 16.8 MB (m, h*d), tf32-rounded
__device__ float g_xr[(size_t)NM*NDM];             // x rounded to tf32
__device__ float g_wr[5][(size_t)NDM*NDM];         // rounded weights, original [k][n] layout

// ---------------------------------------------------------------------------
__device__ __forceinline__ float rna_tf32(float v) {
    uint32_t u;
    asm("cvt.rna.tf32.f32 %0, %1;" : "=r"(u) : "r"(__float_as_uint(v)));
    return __uint_as_float(u);
}
__device__ __forceinline__ uint32_t smem_u32(const void* p) {
    uint32_t a;
    asm("{ .reg .u64 t; cvta.to.shared.u64 t, %1; cvt.u32.u64 %0, t; }" : "=r"(a) : "l"(p));
    return a;
}

// ---------------------------------------------------------------------------
// Pre-passes: round x and weights to tf32 (RNA) into scratch
// ---------------------------------------------------------------------------
__global__ __launch_bounds__(256) void round_x(const float4* __restrict__ x) {
    int i = blockIdx.x * 256 + threadIdx.x;       // 1,048,576 float4
    float4 v = x[i];
    v.x = rna_tf32(v.x); v.y = rna_tf32(v.y); v.z = rna_tf32(v.z); v.w = rna_tf32(v.w);
    ((float4*)g_xr)[i] = v;
}

__global__ __launch_bounds__(256) void wround(
    const float4* __restrict__ w0, const float4* __restrict__ w1,
    const float4* __restrict__ w2, const float4* __restrict__ w3,
    const float4* __restrict__ w4)
{
    int mat = blockIdx.y;
    const float4* W = (mat==0)?w0:(mat==1)?w1:(mat==2)?w2:(mat==3)?w3:w4;
    int i = blockIdx.x * 256 + threadIdx.x;       // 262,144 float4 per matrix
    float4 v = W[i];
    v.x = rna_tf32(v.x); v.y = rna_tf32(v.y); v.z = rna_tf32(v.z); v.w = rna_tf32(v.w);
    ((float4*)g_wr[mat])[i] = v;
}

// ---------------------------------------------------------------------------
// Tensor-core GEMM via mma.sync tf32 (m16n8k8). C = A(128x1024) @ W(1024x128 tile)
// 256 threads, warp grid 4(m) x 2(n), warp tile 32x64, BK=32, 2-stage cp.async.
// mode 0: A=g_xr, W=g_wr[blockIdx.z], scatter to g_proj (b,h,l,d)
// mode 1: A=g_att, W=g_wr[4], row-major to Cout
// ---------------------------------------------------------------------------
#define BM 128
#define BN 128
#define BK 32
#define ASTR 36            // A smem row stride (floats): banks (gid*4+tg) distinct
#define BSTR 136           // B smem row stride (floats): banks (tg*8+gid) distinct
#define AFLOATS (BM*ASTR)  // 4608
#define STG_FLOATS (AFLOATS + BK*BSTR)   // 4608 + 4352 = 8960 (35840 B)

__device__ __forceinline__ void load_stage(
    const float* __restrict__ A, const float* __restrict__ W,
    int m0, int n0, int k0, uint32_t sA, uint32_t sB, int t)
{
#pragma unroll
    for (int i = 0; i < 4; i++) {            // A tile 128x32
        int idx = t + i*256;
        int row = idx >> 3, seg = idx & 7;
        asm volatile("cp.async.cg.shared.global [%0], [%1], 16;"
                     :: "r"(sA + (uint32_t)(row*ASTR + seg*4)*4u),
                        "l"(A + (size_t)(m0 + row)*NDM + k0 + seg*4));
    }
#pragma unroll
    for (int i = 0; i < 4; i++) {            // B tile 32x128 ([k][n])
        int idx = t + i*256;
        int row = idx >> 5, seg = idx & 31;
        asm volatile("cp.async.cg.shared.global [%0], [%1], 16;"
                     :: "r"(sB + (uint32_t)(row*BSTR + seg*4)*4u),
                        "l"(W + (size_t)(k0 + row)*NDM + n0 + seg*4));
    }
}

__global__ __launch_bounds__(256, 2) void gemm_tc(float* __restrict__ Cout, int mode)
{
    extern __shared__ float sm[];
    const uint32_t smb = smem_u32(sm);

    const int t = threadIdx.x;
    const int wid = t >> 5, lane = t & 31;
    const int gid = lane >> 2, tg = lane & 3;
    const int warp_m = (wid >> 1) * 32;
    const int warp_n = (wid & 1) * 64;

    const int mat = (mode == 0) ? (int)blockIdx.z : 4;
    const float* A = (mode == 0) ? g_xr : g_att;
    const float* W = g_wr[mat];
    const int m0 = blockIdx.y * BM, n0 = blockIdx.x * BN;

    float acc[2][8][4];
#pragma unroll
    for (int mt = 0; mt < 2; mt++)
#pragma unroll
        for (int nt = 0; nt < 8; nt++)
#pragma unroll
            for (int c = 0; c < 4; c++) acc[mt][nt][c] = 0.f;

    load_stage(A, W, m0, n0, 0, smb, smb + AFLOATS*4, t);
    asm volatile("cp.async.commit_group;" ::: "memory");

    for (int i = 0; i < NDM/BK; i++) {
        const int s = i & 1;
        if (i < NDM/BK - 1) {
            uint32_t base = smb + (uint32_t)((s^1) * STG_FLOATS) * 4u;
            load_stage(A, W, m0, n0, (i+1)*BK, base, base + AFLOATS*4, t);
            asm volatile("cp.async.commit_group;" ::: "memory");
            asm volatile("cp.async.wait_group 1;" ::: "memory");
        } else {
            asm volatile("cp.async.wait_group 0;" ::: "memory");
        }
        __syncthreads();

        const uint32_t* cA = (const uint32_t*)(sm + s*STG_FLOATS);
        const uint32_t* cB = cA + AFLOATS;
#pragma unroll
        for (int k8 = 0; k8 < 4; k8++) {
            const int kb = k8 * 8;
            uint32_t a[2][4], b[8][2];
#pragma unroll
            for (int mt = 0; mt < 2; mt++) {
                int r0 = warp_m + mt*16 + gid;
                a[mt][0] = cA[r0*ASTR + kb + tg];
                a[mt][1] = cA[(r0+8)*ASTR + kb + tg];
                a[mt][2] = cA[r0*ASTR + kb + tg + 4];
                a[mt][3] = cA[(r0+8)*ASTR + kb + tg + 4];
            }
#pragma unroll
            for (int nt = 0; nt < 8; nt++) {
                int cix = (kb + tg)*BSTR + warp_n + nt*8 + gid;
                b[nt][0] = cB[cix];
                b[nt][1] = cB[cix + 4*BSTR];
            }
#pragma unroll
            for (int mt = 0; mt < 2; mt++)
#pragma unroll
                for (int nt = 0; nt < 8; nt++)
                    asm volatile(
                        "mma.sync.aligned.m16n8k8.row.col.f32.tf32.tf32.f32 "
                        "{%0,%1,%2,%3},{%4,%5,%6,%7},{%8,%9},{%0,%1,%2,%3};"
                        : "+f"(acc[mt][nt][0]), "+f"(acc[mt][nt][1]),
                          "+f"(acc[mt][nt][2]), "+f"(acc[mt][nt][3])
                        : "r"(a[mt][0]), "r"(a[mt][1]), "r"(a[mt][2]), "r"(a[mt][3]),
                          "r"(b[nt][0]), "r"(b[nt][1]));
        }
        __syncthreads();
    }

    // Epilogue: c0,c1 at (row, 2tg), c2,c3 at (row+8, 2tg) — float2 stores
#pragma unroll
    for (int mt = 0; mt < 2; mt++) {
#pragma unroll
        for (int nt = 0; nt < 8; nt++) {
            int col = n0 + warp_n + nt*8 + 2*tg;
            int r0 = m0 + warp_m + mt*16 + gid;
            float* dst0; float* dst1;
            if (mode == 0) {
                int h = col >> 6, d0 = col & 63;
                int b0i = r0 >> 11, l0 = r0 & (NL-1);
                int b1i = (r0+8) >> 11, l1 = (r0+8) & (NL-1);
                dst0 = g_proj[mat] + (((size_t)(b0i*NH + h))*NL + l0)*ND + d0;
                dst1 = g_proj[mat] + (((size_t)(b1i*NH + h))*NL + l1)*ND + d0;
            } else {
                dst0 = Cout + (size_t)r0*NDM + col;
                dst1 = Cout + (size_t)(r0+8)*NDM + col;
            }
            *(float2*)dst0 = make_float2(acc[mt][nt][0], acc[mt][nt][1]);
            *(float2*)dst1 = make_float2(acc[mt][nt][2], acc[mt][nt][3]);
        }
    }
}

// ---------------------------------------------------------------------------
// Flash attention over relational keys + Hadamard with relational queries.
// ---------------------------------------------------------------------------
__device__ __forceinline__ int krow_off(int c) { return c*68 + ((c >> 4) << 3); }

__global__ __launch_bounds__(256) void flash_kernel()
{
    extern __shared__ float fsm[];
    float* qs  = fsm;
    float* ks  = fsm + 4352;
    float* krs = fsm + 4352 + 4384;
    float* Ps  = krs + 4352;

    const int qt = blockIdx.x;
    const int bh = blockIdx.y;
    const float* qp  = g_proj[0] + (size_t)bh*NL*ND;
    const float* kp  = g_proj[1] + (size_t)bh*NL*ND;
    const float* qrp = g_proj[2] + (size_t)bh*NL*ND;
    const float* krp = g_proj[3] + (size_t)bh*NL*ND;

    const int t = threadIdx.x;
    const int r = t >> 2;
    const int lane4 = t & 3;
    const int dcol  = lane4 * 16;

#pragma unroll
    for (int i = 0; i < 4; i++) {
        *(float4*)&qs[r*68 + dcol + i*4] =
            *(const float4*)(qp + (size_t)(qt*64 + r)*ND + dcol + i*4);
    }

    float O[16];
#pragma unroll
    for (int i = 0; i < 16; i++) O[i] = 0.f;
    float mrow = -1e30f, lsum = 0.f;

    const int qi = qt*64 + r;
    __syncthreads();

    for (int j = 0; j <= qt; j++) {
#pragma unroll
        for (int i = 0; i < 4; i++) {
            *(float4*)&ks [krow_off(r) + dcol + i*4] =
                *(const float4*)(kp  + (size_t)(j*64 + r)*ND + dcol + i*4);
            *(float4*)&krs[r*68      + dcol + i*4] =
                *(const float4*)(krp + (size_t)(j*64 + r)*ND + dcol + i*4);
        }
        __syncthreads();

        float s[16];
#pragma unroll
        for (int cc = 0; cc < 16; cc++) s[cc] = 0.f;
#pragma unroll
        for (int k4 = 0; k4 < 16; k4++) {
            float4 qv = *(float4*)&qs[r*68 + k4*4];
#pragma unroll
            for (int cc = 0; cc < 16; cc++) {
                float4 kv = *(float4*)&ks[krow_off(dcol+cc) + k4*4];
                s[cc] += qv.x*kv.x + qv.y*kv.y + qv.z*kv.z + qv.w*kv.w;
            }
        }
#pragma unroll
        for (int cc = 0; cc < 16; cc++) {
            int kj = j*64 + dcol + cc;
            s[cc] = (kj <= qi) ? s[cc]*0.125f : -1e30f;
        }
        float mx = s[0];
#pragma unroll
        for (int cc = 1; cc < 16; cc++) mx = fmaxf(mx, s[cc]);
        mx = fmaxf(mx, __shfl_xor_sync(0xffffffffu, mx, 1));
        mx = fmaxf(mx, __shfl_xor_sync(0xffffffffu, mx, 2));
        float m_new = fmaxf(mrow, mx);
        float corr  = __expf(mrow - m_new);

        float p[16], psum = 0.f;
#pragma unroll
        for (int cc = 0; cc < 16; cc++) { p[cc] = __expf(s[cc] - m_new); psum += p[cc]; }
        psum += __shfl_xor_sync(0xffffffffu, psum, 1);
        psum += __shfl_xor_sync(0xffffffffu, psum, 2);
        lsum = lsum*corr + psum;
        mrow = m_new;
#pragma unroll
        for (int i = 0; i < 16; i++) O[i] *= corr;

#pragma unroll
        for (int i = 0; i < 4; i++)
            *(float4*)&Ps[r*68 + dcol + i*4] =
                make_float4(p[i*4+0], p[i*4+1], p[i*4+2], p[i*4+3]);
        __syncwarp();

#pragma unroll 16
        for (int c = 0; c < 64; c++) {
            float pc = Ps[r*68 + c];
#pragma unroll
            for (int i = 0; i < 4; i++) {
                float4 kv = *(float4*)&krs[c*68 + lane4*4 + i*16];
                O[i*4+0] += pc*kv.x; O[i*4+1] += pc*kv.y;
                O[i*4+2] += pc*kv.z; O[i*4+3] += pc*kv.w;
            }
        }
        __syncthreads();
    }

    float inv = 1.f / lsum;
    int b = bh >> 4, h = bh & 15;
    int li = qt*64 + r;
    const float* qr_row = qrp + (size_t)li*ND;
    float* outp = g_att + ((size_t)(b*NL + li))*NDM + h*64;
#pragma unroll
    for (int i = 0; i < 4; i++) {
        int d = lane4*4 + i*16;
        float4 q4 = *(const float4*)(qr_row + d);
        float4 o;
        o.x = rna_tf32(O[i*4+0]*inv*q4.x); o.y = rna_tf32(O[i*4+1]*inv*q4.y);
        o.z = rna_tf32(O[i*4+2]*inv*q4.z); o.w = rna_tf32(O[i*4+3]*inv*q4.w);
        *(float4*)(outp + d) = o;
    }
}

// ---------------------------------------------------------------------------
extern "C" void kernel_launch(void* const* d_in, const int* in_sizes, int n_in,
                              void* d_out, int out_size)
{
    const float* x   = (const float*)d_in[0];
    const float* wq  = (const float*)d_in[1];
    const float* wk  = (const float*)d_in[2];
    const float* wqr = (const float*)d_in[3];
    const float* wkr = (const float*)d_in[4];
    const float* wo  = (const float*)d_in[5];
    float* out = (float*)d_out;

    // 0) pre-round to tf32
    round_x<<<4096, 256>>>((const float4*)x);
    wround<<<dim3(1024, 5), 256>>>((const float4*)wq, (const float4*)wk,
                                   (const float4*)wqr, (const float4*)wkr,
                                   (const float4*)wo);

    // 1) projections via mma.sync tf32
    const int gsmem = 2 * STG_FLOATS * (int)sizeof(float);   // 71680
    cudaFuncSetAttribute(gemm_tc, cudaFuncAttributeMaxDynamicSharedMemorySize, gsmem);
    gemm_tc<<<dim3(NDM/BN, NM/BM, 4), 256, gsmem>>>(out, 0);

    // 2) flash attention + Hadamard
    const int smem_bytes = (4352 + 4384 + 4352 + 4352) * (int)sizeof(float);
    cudaFuncSetAttribute(flash_kernel, cudaFuncAttributeMaxDynamicSharedMemorySize, smem_bytes);
    flash_kernel<<<dim3(NL/64, NB*NH), 256, smem_bytes>>>();

    // 3) output projection via mma.sync tf32
    gemm_tc<<<dim3(NDM/BN, NM/BM, 1), 256, gsmem>>>(out, 1);
}

// round 5
// speedup vs baseline: 4.9361x; 3.6454x over previous
#include <cuda_runtime.h>
#include <cstdint>

// Problem constants
#define NB 2
#define NL 2048
#define NDM 1024
#define NH 16
#define ND 64
#define NM (NB*NL)   // 4096

// Scratch
// g_proj[0]=q [bh][l][d], g_proj[1]=k TRANSPOSED [bh][d][l], g_proj[2]=qr [bh][l][d], g_proj[3]=kr [bh][l][d]
__device__ float g_proj[4][(size_t)NB*NH*NL*ND];
__device__ float g_att[(size_t)NB*NL*NDM];         // (m, h*d), tf32-rounded
__device__ float g_xr[(size_t)NM*NDM];             // x rounded to tf32
__device__ float g_wr[5][(size_t)NDM*NDM];         // rounded weights [k][n]

// ---------------------------------------------------------------------------
__device__ __forceinline__ float rna_tf32(float v) {
    uint32_t u;
    asm("cvt.rna.tf32.f32 %0, %1;" : "=r"(u) : "r"(__float_as_uint(v)));
    return __uint_as_float(u);
}
__device__ __forceinline__ uint32_t smem_u32(const void* p) {
    uint32_t a;
    asm("{ .reg .u64 t; cvta.to.shared.u64 t, %1; cvt.u32.u64 %0, t; }" : "=r"(a) : "l"(p));
    return a;
}
#define MMA_TF32(d0,d1,d2,d3,a0,a1,a2,a3,b0,b1) \
    asm volatile("mma.sync.aligned.m16n8k8.row.col.f32.tf32.tf32.f32 " \
        "{%0,%1,%2,%3},{%4,%5,%6,%7},{%8,%9},{%0,%1,%2,%3};" \
        : "+f"(d0), "+f"(d1), "+f"(d2), "+f"(d3) \
        : "r"(a0), "r"(a1), "r"(a2), "r"(a3), "r"(b0), "r"(b1))

// ---------------------------------------------------------------------------
// Pre-passes
// ---------------------------------------------------------------------------
__global__ __launch_bounds__(256) void round_x(const float4* __restrict__ x) {
    int i = blockIdx.x * 256 + threadIdx.x;
    float4 v = x[i];
    v.x = rna_tf32(v.x); v.y = rna_tf32(v.y); v.z = rna_tf32(v.z); v.w = rna_tf32(v.w);
    ((float4*)g_xr)[i] = v;
}
__global__ __launch_bounds__(256) void wround(
    const float4* __restrict__ w0, const float4* __restrict__ w1,
    const float4* __restrict__ w2, const float4* __restrict__ w3,
    const float4* __restrict__ w4)
{
    int mat = blockIdx.y;
    const float4* W = (mat==0)?w0:(mat==1)?w1:(mat==2)?w2:(mat==3)?w3:w4;
    int i = blockIdx.x * 256 + threadIdx.x;
    float4 v = W[i];
    v.x = rna_tf32(v.x); v.y = rna_tf32(v.y); v.z = rna_tf32(v.z); v.w = rna_tf32(v.w);
    ((float4*)g_wr[mat])[i] = v;
}

// ---------------------------------------------------------------------------
// Tensor-core GEMM (mma.sync tf32 m16n8k8), 128x128x32 tile, 256 thr, 2-stage.
// mode 0: A=g_xr, W=g_wr[z]; scatter to g_proj (mat 1 transposed, RNA for 0/1/3)
// mode 1: A=g_att, W=g_wr[4]; row-major to Cout
// ---------------------------------------------------------------------------
#define BM 128
#define BN 128
#define BK 32
#define ASTR 36
#define BSTR 136
#define AFLOATS (BM*ASTR)
#define STG_FLOATS (AFLOATS + BK*BSTR)

__device__ __forceinline__ void load_stage(
    const float* __restrict__ A, const float* __restrict__ W,
    int m0, int n0, int k0, uint32_t sA, uint32_t sB, int t)
{
#pragma unroll
    for (int i = 0; i < 4; i++) {
        int idx = t + i*256;
        int row = idx >> 3, seg = idx & 7;
        asm volatile("cp.async.cg.shared.global [%0], [%1], 16;"
                     :: "r"(sA + (uint32_t)(row*ASTR + seg*4)*4u),
                        "l"(A + (size_t)(m0 + row)*NDM + k0 + seg*4));
    }
#pragma unroll
    for (int i = 0; i < 4; i++) {
        int idx = t + i*256;
        int row = idx >> 5, seg = idx & 31;
        asm volatile("cp.async.cg.shared.global [%0], [%1], 16;"
                     :: "r"(sB + (uint32_t)(row*BSTR + seg*4)*4u),
                        "l"(W + (size_t)(k0 + row)*NDM + n0 + seg*4));
    }
}

__global__ __launch_bounds__(256, 2) void gemm_tc(float* __restrict__ Cout, int mode)
{
    extern __shared__ float sm[];
    const uint32_t smb = smem_u32(sm);

    const int t = threadIdx.x;
    const int wid = t >> 5, lane = t & 31;
    const int gid = lane >> 2, tg = lane & 3;
    const int warp_m = (wid >> 1) * 32;
    const int warp_n = (wid & 1) * 64;

    const int mat = (mode == 0) ? (int)blockIdx.z : 4;
    const float* A = (mode == 0) ? g_xr : g_att;
    const float* W = g_wr[mat];
    const int m0 = blockIdx.y * BM, n0 = blockIdx.x * BN;

    float acc[2][8][4];
#pragma unroll
    for (int mt = 0; mt < 2; mt++)
#pragma unroll
        for (int nt = 0; nt < 8; nt++)
#pragma unroll
            for (int c = 0; c < 4; c++) acc[mt][nt][c] = 0.f;

    load_stage(A, W, m0, n0, 0, smb, smb + AFLOATS*4, t);
    asm volatile("cp.async.commit_group;" ::: "memory");

    for (int i = 0; i < NDM/BK; i++) {
        const int s = i & 1;
        if (i < NDM/BK - 1) {
            uint32_t base = smb + (uint32_t)((s^1) * STG_FLOATS) * 4u;
            load_stage(A, W, m0, n0, (i+1)*BK, base, base + AFLOATS*4, t);
            asm volatile("cp.async.commit_group;" ::: "memory");
            asm volatile("cp.async.wait_group 1;" ::: "memory");
        } else {
            asm volatile("cp.async.wait_group 0;" ::: "memory");
        }
        __syncthreads();

        const uint32_t* cA = (const uint32_t*)(sm + s*STG_FLOATS);
        const uint32_t* cB = cA + AFLOATS;
#pragma unroll
        for (int k8 = 0; k8 < 4; k8++) {
            const int kb = k8 * 8;
            uint32_t a[2][4], b[8][2];
#pragma unroll
            for (int mt = 0; mt < 2; mt++) {
                int r0 = warp_m + mt*16 + gid;
                a[mt][0] = cA[r0*ASTR + kb + tg];
                a[mt][1] = cA[(r0+8)*ASTR + kb + tg];
                a[mt][2] = cA[r0*ASTR + kb + tg + 4];
                a[mt][3] = cA[(r0+8)*ASTR + kb + tg + 4];
            }
#pragma unroll
            for (int nt = 0; nt < 8; nt++) {
                int cix = (kb + tg)*BSTR + warp_n + nt*8 + gid;
                b[nt][0] = cB[cix];
                b[nt][1] = cB[cix + 4*BSTR];
            }
#pragma unroll
            for (int mt = 0; mt < 2; mt++)
#pragma unroll
                for (int nt = 0; nt < 8; nt++)
                    MMA_TF32(acc[mt][nt][0], acc[mt][nt][1], acc[mt][nt][2], acc[mt][nt][3],
                             a[mt][0], a[mt][1], a[mt][2], a[mt][3],
                             b[nt][0], b[nt][1]);
        }
        __syncthreads();
    }

#pragma unroll
    for (int mt = 0; mt < 2; mt++) {
#pragma unroll
        for (int nt = 0; nt < 8; nt++) {
            float v0 = acc[mt][nt][0], v1 = acc[mt][nt][1];
            float v2 = acc[mt][nt][2], v3 = acc[mt][nt][3];
            int col = n0 + warp_n + nt*8 + 2*tg;
            int r0 = m0 + warp_m + mt*16 + gid, r1 = r0 + 8;
            if (mode == 1) {
                *(float2*)(Cout + (size_t)r0*NDM + col) = make_float2(v0, v1);
                *(float2*)(Cout + (size_t)r1*NDM + col) = make_float2(v2, v3);
            } else {
                int h = col >> 6, d0 = col & 63;
                int b0i = r0 >> 11, l0 = r0 & (NL-1);
                int b1i = r1 >> 11, l1 = r1 & (NL-1);
                if (mat != 2) { v0=rna_tf32(v0); v1=rna_tf32(v1); v2=rna_tf32(v2); v3=rna_tf32(v3); }
                if (mat == 1) {
                    float* base = g_proj[1];
                    base[((size_t)((b0i*NH+h)*ND + d0  ))*NL + l0] = v0;
                    base[((size_t)((b0i*NH+h)*ND + d0+1))*NL + l0] = v1;
                    base[((size_t)((b1i*NH+h)*ND + d0  ))*NL + l1] = v2;
                    base[((size_t)((b1i*NH+h)*ND + d0+1))*NL + l1] = v3;
                } else {
                    float* base = g_proj[mat];
                    *(float2*)(base + (((size_t)(b0i*NH+h))*NL + l0)*ND + d0) = make_float2(v0, v1);
                    *(float2*)(base + (((size_t)(b1i*NH+h))*NL + l1)*ND + d0) = make_float2(v2, v3);
                }
            }
        }
    }
}

// ---------------------------------------------------------------------------
// Flash attention on tensor cores (mma.sync tf32), Hadamard epilogue.
// Block = (qt, bh): 64-query tile; 128 threads = 4 warps (m16 each).
// S = Q @ K^T via Kt [d][l] tiles; P@Kr via Kr [c][d] tiles; 2-buffer cp.async.
// ---------------------------------------------------------------------------
#define FSTR 72                      // 64-wide row + 8 pad (72%32==8: conflict-free frags)
#define QSTR 72
#define SQ_FLOATS (64*QSTR)          // 4608
#define KT_FLOATS (64*FSTR)          // 4608

__global__ __launch_bounds__(128) void flash_mma()
{
    extern __shared__ float fs[];
    float* sQ = fs;                            // [64][72]
    float* sKt = fs + SQ_FLOATS;               // 2 x [64][72]  (B for S: [d][key])
    float* sKr = sKt + 2*KT_FLOATS;            // 2 x [64][72]  (B for O: [c][d])
    const uint32_t sQb  = smem_u32(sQ);
    const uint32_t sKtb = smem_u32(sKt);
    const uint32_t sKrb = smem_u32(sKr);

    const int qt = blockIdx.x;
    const int bh = blockIdx.y;
    const float* qp  = g_proj[0] + (size_t)bh*NL*ND;
    const float* ktp = g_proj[1] + (size_t)bh*ND*NL;   // transposed [d][l]
    const float* qrp = g_proj[2] + (size_t)bh*NL*ND;
    const float* krp = g_proj[3] + (size_t)bh*NL*ND;

    const int t = threadIdx.x;
    const int wid = t >> 5, lane = t & 31;
    const int gid = lane >> 2, tg = lane & 3;
    const int wm = wid * 16;
    const int quad = lane & ~3;
    const int s_lo = quad + (tg >> 1);
    const int s_hi = s_lo + 2;
    const bool hi_slot = (tg & 1);

    // --- prologue: Q tile + j=0 K/Kr tiles ---
#pragma unroll
    for (int i = 0; i < 8; i++) {
        int idx = t + i*128;                   // 1024 16B-chunks
        int row = idx >> 4, seg = idx & 15;
        asm volatile("cp.async.cg.shared.global [%0], [%1], 16;"
                     :: "r"(sQb + (uint32_t)(row*QSTR + seg*4)*4u),
                        "l"(qp + (size_t)(qt*64 + row)*ND + seg*4));
    }
#pragma unroll
    for (int i = 0; i < 8; i++) {
        int idx = t + i*128;
        int row = idx >> 4, seg = idx & 15;
        asm volatile("cp.async.cg.shared.global [%0], [%1], 16;"
                     :: "r"(sKtb + (uint32_t)(row*FSTR + seg*4)*4u),
                        "l"(ktp + (size_t)row*NL + seg*4));
        asm volatile("cp.async.cg.shared.global [%0], [%1], 16;"
                     :: "r"(sKrb + (uint32_t)(row*FSTR + seg*4)*4u),
                        "l"(krp + (size_t)row*ND + seg*4));
    }
    asm volatile("cp.async.commit_group;" ::: "memory");
    asm volatile("cp.async.wait_group 0;" ::: "memory");
    __syncthreads();

    // Q fragments (resident)
    uint32_t aq[8][4];
    {
        const uint32_t* cQ = (const uint32_t*)sQ;
        int r0 = wm + gid;
#pragma unroll
        for (int k8 = 0; k8 < 8; k8++) {
            aq[k8][0] = cQ[r0*QSTR + k8*8 + tg];
            aq[k8][1] = cQ[(r0+8)*QSTR + k8*8 + tg];
            aq[k8][2] = cQ[r0*QSTR + k8*8 + tg + 4];
            aq[k8][3] = cQ[(r0+8)*QSTR + k8*8 + tg + 4];
        }
    }

    float O[8][4];
#pragma unroll
    for (int q = 0; q < 8; q++) { O[q][0]=0.f; O[q][1]=0.f; O[q][2]=0.f; O[q][3]=0.f; }
    float m0v = -1e30f, m1v = -1e30f, l0v = 0.f, l1v = 0.f;

    const int row0 = qt*64 + wm + gid;         // global query rows
    const int row1 = row0 + 8;

    for (int j = 0; j <= qt; j++) {
        const int s = j & 1;
        if (j < qt) {   // prefetch j+1 into other buffer
            const int sn = s ^ 1;
#pragma unroll
            for (int i = 0; i < 8; i++) {
                int idx = t + i*128;
                int row = idx >> 4, seg = idx & 15;
                asm volatile("cp.async.cg.shared.global [%0], [%1], 16;"
                             :: "r"(sKtb + (uint32_t)(sn*KT_FLOATS + row*FSTR + seg*4)*4u),
                                "l"(ktp + (size_t)row*NL + (j+1)*64 + seg*4));
                asm volatile("cp.async.cg.shared.global [%0], [%1], 16;"
                             :: "r"(sKrb + (uint32_t)(sn*KT_FLOATS + row*FSTR + seg*4)*4u),
                                "l"(krp + (size_t)((j+1)*64 + row)*ND + seg*4));
            }
            asm volatile("cp.async.commit_group;" ::: "memory");
        }

        // ---- S = Q @ Kt ----
        float sc[8][4];
#pragma unroll
        for (int q = 0; q < 8; q++) { sc[q][0]=0.f; sc[q][1]=0.f; sc[q][2]=0.f; sc[q][3]=0.f; }
        {
            const uint32_t* cK = (const uint32_t*)(sKt + s*KT_FLOATS);
#pragma unroll
            for (int k8 = 0; k8 < 8; k8++) {
                uint32_t b[8][2];
#pragma unroll
                for (int q = 0; q < 8; q++) {
                    int cix = (k8*8 + tg)*FSTR + q*8 + gid;
                    b[q][0] = cK[cix];
                    b[q][1] = cK[cix + 4*FSTR];
                }
#pragma unroll
                for (int q = 0; q < 8; q++)
                    MMA_TF32(sc[q][0], sc[q][1], sc[q][2], sc[q][3],
                             aq[k8][0], aq[k8][1], aq[k8][2], aq[k8][3],
                             b[q][0], b[q][1]);
            }
        }

        // ---- scale + mask ----
        const bool diag = (j == qt);
#pragma unroll
        for (int q = 0; q < 8; q++) {
            int c0 = j*64 + q*8 + 2*tg, c1 = c0 + 1;
            sc[q][0] *= 0.125f; sc[q][1] *= 0.125f; sc[q][2] *= 0.125f; sc[q][3] *= 0.125f;
            if (diag) {
                if (c0 > row0) sc[q][0] = -1e30f;
                if (c1 > row0) sc[q][1] = -1e30f;
                if (c0 > row1) sc[q][2] = -1e30f;
                if (c1 > row1) sc[q][3] = -1e30f;
            }
        }

        // ---- online softmax stats ----
        float mx0 = sc[0][0], mx1 = sc[0][2];
#pragma unroll
        for (int q = 0; q < 8; q++) {
            mx0 = fmaxf(mx0, fmaxf(sc[q][0], sc[q][1]));
            mx1 = fmaxf(mx1, fmaxf(sc[q][2], sc[q][3]));
        }
        mx0 = fmaxf(mx0, __shfl_xor_sync(0xffffffffu, mx0, 1));
        mx0 = fmaxf(mx0, __shfl_xor_sync(0xffffffffu, mx0, 2));
        mx1 = fmaxf(mx1, __shfl_xor_sync(0xffffffffu, mx1, 1));
        mx1 = fmaxf(mx1, __shfl_xor_sync(0xffffffffu, mx1, 2));
        float mn0 = fmaxf(m0v, mx0), mn1 = fmaxf(m1v, mx1);
        float cr0 = __expf(m0v - mn0), cr1 = __expf(m1v - mn1);
        m0v = mn0; m1v = mn1;

        float ps0 = 0.f, ps1 = 0.f;
#pragma unroll
        for (int q = 0; q < 8; q++) {
            sc[q][0] = __expf(sc[q][0] - mn0); ps0 += sc[q][0];
            sc[q][1] = __expf(sc[q][1] - mn0); ps0 += sc[q][1];
            sc[q][2] = __expf(sc[q][2] - mn1); ps1 += sc[q][2];
            sc[q][3] = __expf(sc[q][3] - mn1); ps1 += sc[q][3];
        }
        ps0 += __shfl_xor_sync(0xffffffffu, ps0, 1);
        ps0 += __shfl_xor_sync(0xffffffffu, ps0, 2);
        ps1 += __shfl_xor_sync(0xffffffffu, ps1, 1);
        ps1 += __shfl_xor_sync(0xffffffffu, ps1, 2);
        l0v = l0v*cr0 + ps0;
        l1v = l1v*cr1 + ps1;

#pragma unroll
        for (int q = 0; q < 8; q++) {
            O[q][0] *= cr0; O[q][1] *= cr0; O[q][2] *= cr1; O[q][3] *= cr1;
        }

        // ---- convert P accumulator layout -> A fragment layout (quad shuffles) ----
        uint32_t pa[8][4];
#pragma unroll
        for (int q = 0; q < 8; q++) {
            float p0 = rna_tf32(sc[q][0]), p1 = rna_tf32(sc[q][1]);
            float p2 = rna_tf32(sc[q][2]), p3 = rna_tf32(sc[q][3]);
            float t00 = __shfl_sync(0xffffffffu, p0, s_lo);
            float t01 = __shfl_sync(0xffffffffu, p1, s_lo);
            float t20 = __shfl_sync(0xffffffffu, p2, s_lo);
            float t21 = __shfl_sync(0xffffffffu, p3, s_lo);
            float t02 = __shfl_sync(0xffffffffu, p0, s_hi);
            float t12 = __shfl_sync(0xffffffffu, p1, s_hi);
            float t22 = __shfl_sync(0xffffffffu, p2, s_hi);
            float t32 = __shfl_sync(0xffffffffu, p3, s_hi);
            pa[q][0] = __float_as_uint(hi_slot ? t01 : t00);   // (r0, tg)
            pa[q][1] = __float_as_uint(hi_slot ? t21 : t20);   // (r1, tg)
            pa[q][2] = __float_as_uint(hi_slot ? t12 : t02);   // (r0, tg+4)
            pa[q][3] = __float_as_uint(hi_slot ? t32 : t22);   // (r1, tg+4)
        }

        // ---- O += P @ Kr ----
        {
            const uint32_t* cR = (const uint32_t*)(sKr + s*KT_FLOATS);
#pragma unroll
            for (int k8 = 0; k8 < 8; k8++) {
                uint32_t b[8][2];
#pragma unroll
                for (int nt = 0; nt < 8; nt++) {
                    int cix = (k8*8 + tg)*FSTR + nt*8 + gid;
                    b[nt][0] = cR[cix];
                    b[nt][1] = cR[cix + 4*FSTR];
                }
#pragma unroll
                for (int nt = 0; nt < 8; nt++)
                    MMA_TF32(O[nt][0], O[nt][1], O[nt][2], O[nt][3],
                             pa[k8][0], pa[k8][1], pa[k8][2], pa[k8][3],
                             b[nt][0], b[nt][1]);
            }
        }

        if (j < qt) {
            asm volatile("cp.async.wait_group 0;" ::: "memory");
            __syncthreads();
        }
    }

    // ---- epilogue: normalize, Hadamard with qr, write g_att (tf32-rounded) ----
    const float inv0 = 1.f / l0v, inv1 = 1.f / l1v;
    const int b = bh >> 4, h = bh & 15;
    const int li0 = row0, li1 = row1;
    float* out0 = g_att + ((size_t)(b*NL + li0))*NDM + h*64;
    float* out1 = g_att + ((size_t)(b*NL + li1))*NDM + h*64;
#pragma unroll
    for (int q = 0; q < 8; q++) {
        int d = q*8 + 2*tg;
        float2 qr0 = *(const float2*)(qrp + (size_t)li0*ND + d);
        float2 qr1 = *(const float2*)(qrp + (size_t)li1*ND + d);
        float2 o0, o1;
        o0.x = rna_tf32(O[q][0]*inv0*qr0.x); o0.y = rna_tf32(O[q][1]*inv0*qr0.y);
        o1.x = rna_tf32(O[q][2]*inv1*qr1.x); o1.y = rna_tf32(O[q][3]*inv1*qr1.y);
        *(float2*)(out0 + d) = o0;
        *(float2*)(out1 + d) = o1;
    }
}

// ---------------------------------------------------------------------------
extern "C" void kernel_launch(void* const* d_in, const int* in_sizes, int n_in,
                              void* d_out, int out_size)
{
    const float* x   = (const float*)d_in[0];
    const float* wq  = (const float*)d_in[1];
    const float* wk  = (const float*)d_in[2];
    const float* wqr = (const float*)d_in[3];
    const float* wkr = (const float*)d_in[4];
    const float* wo  = (const float*)d_in[5];
    float* out = (float*)d_out;

    round_x<<<4096, 256>>>((const float4*)x);
    wround<<<dim3(1024, 5), 256>>>((const float4*)wq, (const float4*)wk,
                                   (const float4*)wqr, (const float4*)wkr,
                                   (const float4*)wo);

    const int gsmem = 2 * STG_FLOATS * (int)sizeof(float);
    cudaFuncSetAttribute(gemm_tc, cudaFuncAttributeMaxDynamicSharedMemorySize, gsmem);
    gemm_tc<<<dim3(NDM/BN, NM/BM, 4), 256, gsmem>>>(out, 0);

    const int fsmem = (SQ_FLOATS + 4*KT_FLOATS) * (int)sizeof(float);   // 92160
    cudaFuncSetAttribute(flash_mma, cudaFuncAttributeMaxDynamicSharedMemorySize, fsmem);
    flash_mma<<<dim3(NL/64, NB*NH), 128, fsmem>>>();

    gemm_tc<<<dim3(NDM/BN, NM/BM, 1), 256, gsmem>>>(out, 1);
}

// round 6
// speedup vs baseline: 5.0974x; 1.0327x over previous
#include <cuda_runtime.h>
#include <cstdint>

// Problem constants
#define NB 2
#define NL 2048
#define NDM 1024
#define NH 16
#define ND 64
#define NM (NB*NL)   // 4096

// Scratch
// g_proj[0]=q [bh][l][d], g_proj[1]=k TRANSPOSED [bh][d][l], g_proj[2]=qr [bh][l][d], g_proj[3]=kr [bh][l][d]
__device__ float g_proj[4][(size_t)NB*NH*NL*ND];
__device__ float g_att[(size_t)NB*NL*NDM];         // (m, h*d), tf32-rounded
__device__ float g_xr[(size_t)NM*NDM];             // x rounded to tf32
__device__ float g_wr[5][(size_t)NDM*NDM];         // rounded weights [k][n]

// ---------------------------------------------------------------------------
__device__ __forceinline__ float rna_tf32(float v) {
    uint32_t u;
    asm("cvt.rna.tf32.f32 %0, %1;" : "=r"(u) : "r"(__float_as_uint(v)));
    return __uint_as_float(u);
}
__device__ __forceinline__ uint32_t smem_u32(const void* p) {
    uint32_t a;
    asm("{ .reg .u64 t; cvta.to.shared.u64 t, %1; cvt.u32.u64 %0, t; }" : "=r"(a) : "l"(p));
    return a;
}
#define MMA_TF32(d0,d1,d2,d3,a0,a1,a2,a3,b0,b1) \
    asm volatile("mma.sync.aligned.m16n8k8.row.col.f32.tf32.tf32.f32 " \
        "{%0,%1,%2,%3},{%4,%5,%6,%7},{%8,%9},{%0,%1,%2,%3};" \
        : "+f"(d0), "+f"(d1), "+f"(d2), "+f"(d3) \
        : "r"(a0), "r"(a1), "r"(a2), "r"(a3), "r"(b0), "r"(b1))

// ---------------------------------------------------------------------------
// Pre-passes
// ---------------------------------------------------------------------------
__global__ __launch_bounds__(256) void round_x(const float4* __restrict__ x) {
    int i = blockIdx.x * 256 + threadIdx.x;
    float4 v = x[i];
    v.x = rna_tf32(v.x); v.y = rna_tf32(v.y); v.z = rna_tf32(v.z); v.w = rna_tf32(v.w);
    ((float4*)g_xr)[i] = v;
}
__global__ __launch_bounds__(256) void wround(
    const float4* __restrict__ w0, const float4* __restrict__ w1,
    const float4* __restrict__ w2, const float4* __restrict__ w3,
    const float4* __restrict__ w4)
{
    int mat = blockIdx.y;
    const float4* W = (mat==0)?w0:(mat==1)?w1:(mat==2)?w2:(mat==3)?w3:w4;
    int i = blockIdx.x * 256 + threadIdx.x;
    float4 v = W[i];
    v.x = rna_tf32(v.x); v.y = rna_tf32(v.y); v.z = rna_tf32(v.z); v.w = rna_tf32(v.w);
    ((float4*)g_wr[mat])[i] = v;
}

// ---------------------------------------------------------------------------
// Tensor-core GEMM (mma.sync tf32 m16n8k8), 128x128x32 tile, 256 thr, 3-stage.
// mode 0: A=g_xr, W=g_wr[z]; scatter to g_proj (mat 1 transposed, RNA for 0/1/3)
// mode 1: A=g_att, W=g_wr[4]; row-major to Cout
// ---------------------------------------------------------------------------
#define BM 128
#define BN 128
#define BK 32
#define ASTR 36
#define BSTR 136
#define AFLOATS (BM*ASTR)
#define STG_FLOATS (AFLOATS + BK*BSTR)
#define NITER (NDM/BK)

__device__ __forceinline__ void load_stage(
    const float* __restrict__ A, const float* __restrict__ W,
    int m0, int n0, int k0, uint32_t sA, uint32_t sB, int t)
{
#pragma unroll
    for (int i = 0; i < 4; i++) {
        int idx = t + i*256;
        int row = idx >> 3, seg = idx & 7;
        asm volatile("cp.async.cg.shared.global [%0], [%1], 16;"
                     :: "r"(sA + (uint32_t)(row*ASTR + seg*4)*4u),
                        "l"(A + (size_t)(m0 + row)*NDM + k0 + seg*4));
    }
#pragma unroll
    for (int i = 0; i < 4; i++) {
        int idx = t + i*256;
        int row = idx >> 5, seg = idx & 31;
        asm volatile("cp.async.cg.shared.global [%0], [%1], 16;"
                     :: "r"(sB + (uint32_t)(row*BSTR + seg*4)*4u),
                        "l"(W + (size_t)(k0 + row)*NDM + n0 + seg*4));
    }
}

__global__ __launch_bounds__(256, 2) void gemm_tc(float* __restrict__ Cout, int mode)
{
    extern __shared__ float sm[];
    const uint32_t smb = smem_u32(sm);

    const int t = threadIdx.x;
    const int wid = t >> 5, lane = t & 31;
    const int gid = lane >> 2, tg = lane & 3;
    const int warp_m = (wid >> 1) * 32;
    const int warp_n = (wid & 1) * 64;

    const int mat = (mode == 0) ? (int)blockIdx.z : 4;
    const float* A = (mode == 0) ? g_xr : g_att;
    const float* W = g_wr[mat];
    const int m0 = blockIdx.y * BM, n0 = blockIdx.x * BN;

    float acc[2][8][4];
#pragma unroll
    for (int mt = 0; mt < 2; mt++)
#pragma unroll
        for (int nt = 0; nt < 8; nt++)
#pragma unroll
            for (int c = 0; c < 4; c++) acc[mt][nt][c] = 0.f;

    // prologue: stages 0,1 -> groups G0,G1
#pragma unroll
    for (int p = 0; p < 2; p++) {
        uint32_t base = smb + (uint32_t)(p * STG_FLOATS) * 4u;
        load_stage(A, W, m0, n0, p * BK, base, base + AFLOATS*4, t);
        asm volatile("cp.async.commit_group;" ::: "memory");
    }
    asm volatile("cp.async.wait_group 1;" ::: "memory");   // G0 complete
    __syncthreads();

    for (int i = 0; i < NITER; i++) {
        const int s = i % 3;
        // issue load for i+2 into stage (i+2)%3 (last computed at iter i-1, behind barrier)
        if (i + 2 < NITER) {
            uint32_t base = smb + (uint32_t)(((i+2)%3) * STG_FLOATS) * 4u;
            load_stage(A, W, m0, n0, (i+2)*BK, base, base + AFLOATS*4, t);
        }
        asm volatile("cp.async.commit_group;" ::: "memory");   // G_{i+2} (maybe empty)

        const uint32_t* cA = (const uint32_t*)(sm + s*STG_FLOATS);
        const uint32_t* cB = cA + AFLOATS;
#pragma unroll
        for (int k8 = 0; k8 < 4; k8++) {
            const int kb = k8 * 8;
            uint32_t a[2][4], b[8][2];
#pragma unroll
            for (int mt = 0; mt < 2; mt++) {
                int r0 = warp_m + mt*16 + gid;
                a[mt][0] = cA[r0*ASTR + kb + tg];
                a[mt][1] = cA[(r0+8)*ASTR + kb + tg];
                a[mt][2] = cA[r0*ASTR + kb + tg + 4];
                a[mt][3] = cA[(r0+8)*ASTR + kb + tg + 4];
            }
#pragma unroll
            for (int nt = 0; nt < 8; nt++) {
                int cix = (kb + tg)*BSTR + warp_n + nt*8 + gid;
                b[nt][0] = cB[cix];
                b[nt][1] = cB[cix + 4*BSTR];
            }
#pragma unroll
            for (int mt = 0; mt < 2; mt++)
#pragma unroll
                for (int nt = 0; nt < 8; nt++)
                    MMA_TF32(acc[mt][nt][0], acc[mt][nt][1], acc[mt][nt][2], acc[mt][nt][3],
                             a[mt][0], a[mt][1], a[mt][2], a[mt][3],
                             b[nt][0], b[nt][1]);
        }

        asm volatile("cp.async.wait_group 1;" ::: "memory");   // G_{i+1} complete
        __syncthreads();
    }

#pragma unroll
    for (int mt = 0; mt < 2; mt++) {
#pragma unroll
        for (int nt = 0; nt < 8; nt++) {
            float v0 = acc[mt][nt][0], v1 = acc[mt][nt][1];
            float v2 = acc[mt][nt][2], v3 = acc[mt][nt][3];
            int col = n0 + warp_n + nt*8 + 2*tg;
            int r0 = m0 + warp_m + mt*16 + gid, r1 = r0 + 8;
            if (mode == 1) {
                *(float2*)(Cout + (size_t)r0*NDM + col) = make_float2(v0, v1);
                *(float2*)(Cout + (size_t)r1*NDM + col) = make_float2(v2, v3);
            } else {
                int h = col >> 6, d0 = col & 63;
                int b0i = r0 >> 11, l0 = r0 & (NL-1);
                int b1i = r1 >> 11, l1 = r1 & (NL-1);
                if (mat != 2) { v0=rna_tf32(v0); v1=rna_tf32(v1); v2=rna_tf32(v2); v3=rna_tf32(v3); }
                if (mat == 1) {
                    float* base = g_proj[1];
                    base[((size_t)((b0i*NH+h)*ND + d0  ))*NL + l0] = v0;
                    base[((size_t)((b0i*NH+h)*ND + d0+1))*NL + l0] = v1;
                    base[((size_t)((b1i*NH+h)*ND + d0  ))*NL + l1] = v2;
                    base[((size_t)((b1i*NH+h)*ND + d0+1))*NL + l1] = v3;
                } else {
                    float* base = g_proj[mat];
                    *(float2*)(base + (((size_t)(b0i*NH+h))*NL + l0)*ND + d0) = make_float2(v0, v1);
                    *(float2*)(base + (((size_t)(b1i*NH+h))*NL + l1)*ND + d0) = make_float2(v2, v3);
                }
            }
        }
    }
}

// ---------------------------------------------------------------------------
// Flash attention on tensor cores (mma.sync tf32), Hadamard epilogue.
// Block = (qt, bh): 64-query tile; 128 threads = 4 warps (m16 each).
// Q staged through the Kt stage-1 buffer (freed before first prefetch).
// smem = 4 x 4608 floats = 73728 B -> 3 CTAs/SM.
// ---------------------------------------------------------------------------
#define FSTR 72
#define KT_FLOATS (64*FSTR)          // 4608

__global__ __launch_bounds__(128, 3) void flash_mma()
{
    extern __shared__ float fs[];
    float* sKt = fs;                           // 2 x [64][72]  (B for S: [d][key])
    float* sQ  = fs + KT_FLOATS;               // overlaps Kt stage 1
    float* sKr = fs + 2*KT_FLOATS;             // 2 x [64][72]  (B for O: [c][d])
    const uint32_t sKtb = smem_u32(sKt);
    const uint32_t sQb  = smem_u32(sQ);
    const uint32_t sKrb = smem_u32(sKr);

    const int qt = (int)(gridDim.x - 1 - blockIdx.x);   // heavy tiles first
    const int bh = blockIdx.y;
    const float* qp  = g_proj[0] + (size_t)bh*NL*ND;
    const float* ktp = g_proj[1] + (size_t)bh*ND*NL;   // transposed [d][l]
    const float* qrp = g_proj[2] + (size_t)bh*NL*ND;
    const float* krp = g_proj[3] + (size_t)bh*NL*ND;

    const int t = threadIdx.x;
    const int wid = t >> 5, lane = t & 31;
    const int gid = lane >> 2, tg = lane & 3;
    const int wm = wid * 16;
    const int quad = lane & ~3;
    const int s_lo = quad + (tg >> 1);
    const int s_hi = s_lo + 2;
    const bool hi_slot = (tg & 1);

    // --- prologue: Q tile (into Kt stage-1 area) + j=0 K/Kr tiles (stage 0) ---
#pragma unroll
    for (int i = 0; i < 8; i++) {
        int idx = t + i*128;                   // 1024 16B-chunks
        int row = idx >> 4, seg = idx & 15;
        asm volatile("cp.async.cg.shared.global [%0], [%1], 16;"
                     :: "r"(sQb + (uint32_t)(row*FSTR + seg*4)*4u),
                        "l"(qp + (size_t)(qt*64 + row)*ND + seg*4));
    }
#pragma unroll
    for (int i = 0; i < 8; i++) {
        int idx = t + i*128;
        int row = idx >> 4, seg = idx & 15;
        asm volatile("cp.async.cg.shared.global [%0], [%1], 16;"
                     :: "r"(sKtb + (uint32_t)(row*FSTR + seg*4)*4u),
                        "l"(ktp + (size_t)row*NL + seg*4));
        asm volatile("cp.async.cg.shared.global [%0], [%1], 16;"
                     :: "r"(sKrb + (uint32_t)(row*FSTR + seg*4)*4u),
                        "l"(krp + (size_t)row*ND + seg*4));
    }
    asm volatile("cp.async.commit_group;" ::: "memory");
    asm volatile("cp.async.wait_group 0;" ::: "memory");
    __syncthreads();

    // Q fragments (resident in registers)
    uint32_t aq[8][4];
    {
        const uint32_t* cQ = (const uint32_t*)sQ;
        int r0 = wm + gid;
#pragma unroll
        for (int k8 = 0; k8 < 8; k8++) {
            aq[k8][0] = cQ[r0*FSTR + k8*8 + tg];
            aq[k8][1] = cQ[(r0+8)*FSTR + k8*8 + tg];
            aq[k8][2] = cQ[r0*FSTR + k8*8 + tg + 4];
            aq[k8][3] = cQ[(r0+8)*FSTR + k8*8 + tg + 4];
        }
    }
    __syncthreads();   // Q reads done in ALL threads before stage-1 prefetch may overwrite

    float O[8][4];
#pragma unroll
    for (int q = 0; q < 8; q++) { O[q][0]=0.f; O[q][1]=0.f; O[q][2]=0.f; O[q][3]=0.f; }
    float m0v = -1e30f, m1v = -1e30f, l0v = 0.f, l1v = 0.f;

    const int row0 = qt*64 + wm + gid;         // global query rows
    const int row1 = row0 + 8;

    for (int j = 0; j <= qt; j++) {
        const int s = j & 1;
        if (j < qt) {   // prefetch j+1 into other buffer
            const int sn = s ^ 1;
#pragma unroll
            for (int i = 0; i < 8; i++) {
                int idx = t + i*128;
                int row = idx >> 4, seg = idx & 15;
                asm volatile("cp.async.cg.shared.global [%0], [%1], 16;"
                             :: "r"(sKtb + (uint32_t)(sn*KT_FLOATS + row*FSTR + seg*4)*4u),
                                "l"(ktp + (size_t)row*NL + (j+1)*64 + seg*4));
                asm volatile("cp.async.cg.shared.global [%0], [%1], 16;"
                             :: "r"(sKrb + (uint32_t)(sn*KT_FLOATS + row*FSTR + seg*4)*4u),
                                "l"(krp + (size_t)((j+1)*64 + row)*ND + seg*4));
            }
            asm volatile("cp.async.commit_group;" ::: "memory");
        }

        // ---- S = Q @ Kt ----
        float sc[8][4];
#pragma unroll
        for (int q = 0; q < 8; q++) { sc[q][0]=0.f; sc[q][1]=0.f; sc[q][2]=0.f; sc[q][3]=0.f; }
        {
            const uint32_t* cK = (const uint32_t*)(sKt + s*KT_FLOATS);
#pragma unroll
            for (int k8 = 0; k8 < 8; k8++) {
                uint32_t b[8][2];
#pragma unroll
                for (int q = 0; q < 8; q++) {
                    int cix = (k8*8 + tg)*FSTR + q*8 + gid;
                    b[q][0] = cK[cix];
                    b[q][1] = cK[cix + 4*FSTR];
                }
#pragma unroll
                for (int q = 0; q < 8; q++)
                    MMA_TF32(sc[q][0], sc[q][1], sc[q][2], sc[q][3],
                             aq[k8][0], aq[k8][1], aq[k8][2], aq[k8][3],
                             b[q][0], b[q][1]);
            }
        }

        // ---- scale + mask ----
        const bool diag = (j == qt);
#pragma unroll
        for (int q = 0; q < 8; q++) {
            int c0 = j*64 + q*8 + 2*tg, c1 = c0 + 1;
            sc[q][0] *= 0.125f; sc[q][1] *= 0.125f; sc[q][2] *= 0.125f; sc[q][3] *= 0.125f;
            if (diag) {
                if (c0 > row0) sc[q][0] = -1e30f;
                if (c1 > row0) sc[q][1] = -1e30f;
                if (c0 > row1) sc[q][2] = -1e30f;
                if (c1 > row1) sc[q][3] = -1e30f;
            }
        }

        // ---- online softmax stats ----
        float mx0 = sc[0][0], mx1 = sc[0][2];
#pragma unroll
        for (int q = 0; q < 8; q++) {
            mx0 = fmaxf(mx0, fmaxf(sc[q][0], sc[q][1]));
            mx1 = fmaxf(mx1, fmaxf(sc[q][2], sc[q][3]));
        }
        mx0 = fmaxf(mx0, __shfl_xor_sync(0xffffffffu, mx0, 1));
        mx0 = fmaxf(mx0, __shfl_xor_sync(0xffffffffu, mx0, 2));
        mx1 = fmaxf(mx1, __shfl_xor_sync(0xffffffffu, mx1, 1));
        mx1 = fmaxf(mx1, __shfl_xor_sync(0xffffffffu, mx1, 2));
        float mn0 = fmaxf(m0v, mx0), mn1 = fmaxf(m1v, mx1);
        float cr0 = __expf(m0v - mn0), cr1 = __expf(m1v - mn1);
        m0v = mn0; m1v = mn1;

        float ps0 = 0.f, ps1 = 0.f;
#pragma unroll
        for (int q = 0; q < 8; q++) {
            sc[q][0] = __expf(sc[q][0] - mn0); ps0 += sc[q][0];
            sc[q][1] = __expf(sc[q][1] - mn0); ps0 += sc[q][1];
            sc[q][2] = __expf(sc[q][2] - mn1); ps1 += sc[q][2];
            sc[q][3] = __expf(sc[q][3] - mn1); ps1 += sc[q][3];
        }
        ps0 += __shfl_xor_sync(0xffffffffu, ps0, 1);
        ps0 += __shfl_xor_sync(0xffffffffu, ps0, 2);
        ps1 += __shfl_xor_sync(0xffffffffu, ps1, 1);
        ps1 += __shfl_xor_sync(0xffffffffu, ps1, 2);
        l0v = l0v*cr0 + ps0;
        l1v = l1v*cr1 + ps1;

#pragma unroll
        for (int q = 0; q < 8; q++) {
            O[q][0] *= cr0; O[q][1] *= cr0; O[q][2] *= cr1; O[q][3] *= cr1;
        }

        // ---- convert P accumulator layout -> A fragment layout (quad shuffles) ----
        uint32_t pa[8][4];
#pragma unroll
        for (int q = 0; q < 8; q++) {
            float p0 = rna_tf32(sc[q][0]), p1 = rna_tf32(sc[q][1]);
            float p2 = rna_tf32(sc[q][2]), p3 = rna_tf32(sc[q][3]);
            float t00 = __shfl_sync(0xffffffffu, p0, s_lo);
            float t01 = __shfl_sync(0xffffffffu, p1, s_lo);
            float t20 = __shfl_sync(0xffffffffu, p2, s_lo);
            float t21 = __shfl_sync(0xffffffffu, p3, s_lo);
            float t02 = __shfl_sync(0xffffffffu, p0, s_hi);
            float t12 = __shfl_sync(0xffffffffu, p1, s_hi);
            float t22 = __shfl_sync(0xffffffffu, p2, s_hi);
            float t32 = __shfl_sync(0xffffffffu, p3, s_hi);
            pa[q][0] = __float_as_uint(hi_slot ? t01 : t00);   // (r0, tg)
            pa[q][1] = __float_as_uint(hi_slot ? t21 : t20);   // (r1, tg)
            pa[q][2] = __float_as_uint(hi_slot ? t12 : t02);   // (r0, tg+4)
            pa[q][3] = __float_as_uint(hi_slot ? t32 : t22);   // (r1, tg+4)
        }

        // ---- O += P @ Kr ----
        {
            const uint32_t* cR = (const uint32_t*)(sKr + s*KT_FLOATS);
#pragma unroll
            for (int k8 = 0; k8 < 8; k8++) {
                uint32_t b[8][2];
#pragma unroll
                for (int nt = 0; nt < 8; nt++) {
                    int cix = (k8*8 + tg)*FSTR + nt*8 + gid;
                    b[nt][0] = cR[cix];
                    b[nt][1] = cR[cix + 4*FSTR];
                }
#pragma unroll
                for (int nt = 0; nt < 8; nt++)
                    MMA_TF32(O[nt][0], O[nt][1], O[nt][2], O[nt][3],
                             pa[k8][0], pa[k8][1], pa[k8][2], pa[k8][3],
                             b[nt][0], b[nt][1]);
            }
        }

        if (j < qt) {
            asm volatile("cp.async.wait_group 0;" ::: "memory");
            __syncthreads();
        }
    }

    // ---- epilogue: normalize, Hadamard with qr, write g_att (tf32-rounded) ----
    const float inv0 = 1.f / l0v, inv1 = 1.f / l1v;
    const int b = bh >> 4, h = bh & 15;
    const int li0 = row0, li1 = row1;
    float* out0 = g_att + ((size_t)(b*NL + li0))*NDM + h*64;
    float* out1 = g_att + ((size_t)(b*NL + li1))*NDM + h*64;
#pragma unroll
    for (int q = 0; q < 8; q++) {
        int d = q*8 + 2*tg;
        float2 qr0 = *(const float2*)(qrp + (size_t)li0*ND + d);
        float2 qr1 = *(const float2*)(qrp + (size_t)li1*ND + d);
        float2 o0, o1;
        o0.x = rna_tf32(O[q][0]*inv0*qr0.x); o0.y = rna_tf32(O[q][1]*inv0*qr0.y);
        o1.x = rna_tf32(O[q][2]*inv1*qr1.x); o1.y = rna_tf32(O[q][3]*inv1*qr1.y);
        *(float2*)(out0 + d) = o0;
        *(float2*)(out1 + d) = o1;
    }
}

// ---------------------------------------------------------------------------
extern "C" void kernel_launch(void* const* d_in, const int* in_sizes, int n_in,
                              void* d_out, int out_size)
{
    const float* x   = (const float*)d_in[0];
    const float* wq  = (const float*)d_in[1];
    const float* wk  = (const float*)d_in[2];
    const float* wqr = (const float*)d_in[3];
    const float* wkr = (const float*)d_in[4];
    const float* wo  = (const float*)d_in[5];
    float* out = (float*)d_out;

    round_x<<<4096, 256>>>((const float4*)x);
    wround<<<dim3(1024, 5), 256>>>((const float4*)wq, (const float4*)wk,
                                   (const float4*)wqr, (const float4*)wkr,
                                   (const float4*)wo);

    const int gsmem = 3 * STG_FLOATS * (int)sizeof(float);   // 107520
    cudaFuncSetAttribute(gemm_tc, cudaFuncAttributeMaxDynamicSharedMemorySize, gsmem);
    gemm_tc<<<dim3(NDM/BN, NM/BM, 4), 256, gsmem>>>(out, 0);

    const int fsmem = 4 * KT_FLOATS * (int)sizeof(float);    // 73728
    cudaFuncSetAttribute(flash_mma, cudaFuncAttributeMaxDynamicSharedMemorySize, fsmem);
    flash_mma<<<dim3(NL/64, NB*NH), 128, fsmem>>>();

    gemm_tc<<<dim3(NDM/BN, NM/BM, 1), 256, gsmem>>>(out, 1);
}

// round 7
// speedup vs baseline: 5.2993x; 1.0396x over previous
#include <cuda_runtime.h>
#include <cstdint>

// Problem constants
#define NB 2
#define NL 2048
#define NDM 1024
#define NH 16
#define ND 64
#define NM (NB*NL)   // 4096

// Scratch
// g_proj[0]=q [bh][l][d], g_proj[1]=k [bh][l][d] (natural), g_proj[2]=qr [bh][l][d],
// g_proj[3]=kr TRANSPOSED [bh][d][l]
__device__ float g_proj[4][(size_t)NB*NH*NL*ND];
__device__ float g_att[(size_t)NB*NL*NDM];         // (m, h*d), tf32-rounded
__device__ float g_xr[(size_t)NM*NDM];             // x rounded to tf32
__device__ float g_wt[5][(size_t)NDM*NDM];         // transposed+rounded weights [n][k]

// ---------------------------------------------------------------------------
__device__ __forceinline__ float rna_tf32(float v) {
    uint32_t u;
    asm("cvt.rna.tf32.f32 %0, %1;" : "=r"(u) : "r"(__float_as_uint(v)));
    return __uint_as_float(u);
}
__device__ __forceinline__ uint32_t smem_u32(const void* p) {
    uint32_t a;
    asm("{ .reg .u64 t; cvta.to.shared.u64 t, %1; cvt.u32.u64 %0, t; }" : "=r"(a) : "l"(p));
    return a;
}
#define MMA_TF32(d0,d1,d2,d3,a0,a1,a2,a3,b0,b1) \
    asm volatile("mma.sync.aligned.m16n8k8.row.col.f32.tf32.tf32.f32 " \
        "{%0,%1,%2,%3},{%4,%5,%6,%7},{%8,%9},{%0,%1,%2,%3};" \
        : "+f"(d0), "+f"(d1), "+f"(d2), "+f"(d3) \
        : "r"(a0), "r"(a1), "r"(a2), "r"(a3), "r"(b0), "r"(b1))
#define LDSM_X4(r0,r1,r2,r3,addr) \
    asm volatile("ldmatrix.sync.aligned.m8n8.x4.shared.b16 {%0,%1,%2,%3}, [%4];" \
        : "=r"(r0), "=r"(r1), "=r"(r2), "=r"(r3) : "r"(addr))

// ---------------------------------------------------------------------------
// Pre-passes
// ---------------------------------------------------------------------------
__global__ __launch_bounds__(256) void round_x(const float4* __restrict__ x) {
    int i = blockIdx.x * 256 + threadIdx.x;
    float4 v = x[i];
    v.x = rna_tf32(v.x); v.y = rna_tf32(v.y); v.z = rna_tf32(v.z); v.w = rna_tf32(v.w);
    ((float4*)g_xr)[i] = v;
}
// transpose + round weights: g_wt[mat][n][k]
__global__ __launch_bounds__(256) void wtrans(
    const float* __restrict__ w0, const float* __restrict__ w1,
    const float* __restrict__ w2, const float* __restrict__ w3,
    const float* __restrict__ w4)
{
    __shared__ float tl[32][33];
    const float* W = (blockIdx.z==0)?w0:(blockIdx.z==1)?w1:(blockIdx.z==2)?w2:(blockIdx.z==3)?w3:w4;
    float* Wt = g_wt[blockIdx.z];
    int n0 = blockIdx.x * 32, k0 = blockIdx.y * 32;
    int tx = threadIdx.x & 31, ty = threadIdx.x >> 5;   // 32x8
#pragma unroll
    for (int j = 0; j < 4; j++)
        tl[ty + j*8][tx] = W[(size_t)(k0 + ty + j*8)*NDM + n0 + tx];
    __syncthreads();
#pragma unroll
    for (int j = 0; j < 4; j++)
        Wt[(size_t)(n0 + ty + j*8)*NDM + k0 + tx] = rna_tf32(tl[tx][ty + j*8]);
}

// ---------------------------------------------------------------------------
// Tensor-core GEMM (mma.sync tf32 m16n8k8), 128x128x32 tile, 256 thr, 3-stage.
// A [m][k] stride 36; B = W^T [n][k] stride 36. Fragments via ldmatrix.
// mode 0: A=g_xr, W=g_wt[z]; scatter to g_proj (mat 3 transposed; RNA for 0/1/3)
// mode 1: A=g_att, W=g_wt[4]; row-major to Cout
// ---------------------------------------------------------------------------
#define BM 128
#define BN 128
#define BK 32
#define TSTR 36
#define AFLOATS (BM*TSTR)                 // 4608
#define STG_FLOATS (2*AFLOATS)            // 9216 (36864 B)
#define NITER (NDM/BK)

__device__ __forceinline__ void load_stage(
    const float* __restrict__ A, const float* __restrict__ Wt,
    int m0, int n0, int k0, uint32_t sA, uint32_t sB, int t)
{
#pragma unroll
    for (int i = 0; i < 4; i++) {
        int idx = t + i*256;
        int row = idx >> 3, seg = idx & 7;
        uint32_t off = (uint32_t)(row*TSTR + seg*4)*4u;
        asm volatile("cp.async.cg.shared.global [%0], [%1], 16;"
                     :: "r"(sA + off), "l"(A + (size_t)(m0 + row)*NDM + k0 + seg*4));
        asm volatile("cp.async.cg.shared.global [%0], [%1], 16;"
                     :: "r"(sB + off), "l"(Wt + (size_t)(n0 + row)*NDM + k0 + seg*4));
    }
}

__global__ __launch_bounds__(256, 2) void gemm_tc(float* __restrict__ Cout, int mode)
{
    extern __shared__ float sm[];
    const uint32_t smb = smem_u32(sm);

    const int t = threadIdx.x;
    const int wid = t >> 5, lane = t & 31;
    const int gid = lane >> 2, tg = lane & 3;
    const int g8 = lane >> 3, lr = lane & 7;
    const int warp_m = (wid >> 1) * 32;
    const int warp_n = (wid & 1) * 64;

    const int mat = (mode == 0) ? (int)blockIdx.z : 4;
    const float* A = (mode == 0) ? g_xr : g_att;
    const float* W = g_wt[mat];
    const int m0 = blockIdx.y * BM, n0 = blockIdx.x * BN;

    // LDSM per-thread byte offsets (within a stage)
    uint32_t aoff[2], boff[4];
#pragma unroll
    for (int mt = 0; mt < 2; mt++)
        aoff[mt] = (uint32_t)(((warp_m + mt*16 + (g8&1)*8 + lr)*TSTR + (g8>>1)*4) * 4);
#pragma unroll
    for (int i = 0; i < 4; i++)
        boff[i] = (uint32_t)(AFLOATS*4) +
                  (uint32_t)(((warp_n + (i*2 + (g8>>1))*8 + lr)*TSTR + (g8&1)*4) * 4);

    float acc[2][8][4];
#pragma unroll
    for (int mt = 0; mt < 2; mt++)
#pragma unroll
        for (int nt = 0; nt < 8; nt++)
#pragma unroll
            for (int c = 0; c < 4; c++) acc[mt][nt][c] = 0.f;

    // prologue: stages 0,1 -> groups G0,G1
#pragma unroll
    for (int p = 0; p < 2; p++) {
        uint32_t base = smb + (uint32_t)(p * STG_FLOATS) * 4u;
        load_stage(A, W, m0, n0, p * BK, base, base + AFLOATS*4, t);
        asm volatile("cp.async.commit_group;" ::: "memory");
    }
    asm volatile("cp.async.wait_group 1;" ::: "memory");
    __syncthreads();

    for (int i = 0; i < NITER; i++) {
        const int s = i % 3;
        if (i + 2 < NITER) {
            uint32_t base = smb + (uint32_t)(((i+2)%3) * STG_FLOATS) * 4u;
            load_stage(A, W, m0, n0, (i+2)*BK, base, base + AFLOATS*4, t);
        }
        asm volatile("cp.async.commit_group;" ::: "memory");

        const uint32_t stb = smb + (uint32_t)(s * STG_FLOATS) * 4u;
#pragma unroll
        for (int k8 = 0; k8 < 4; k8++) {
            const uint32_t kb = (uint32_t)k8 * 32u;   // 8 floats
            uint32_t a[2][4], b[8][2];
#pragma unroll
            for (int mt = 0; mt < 2; mt++)
                LDSM_X4(a[mt][0], a[mt][1], a[mt][2], a[mt][3], stb + aoff[mt] + kb);
#pragma unroll
            for (int i4 = 0; i4 < 4; i4++)
                LDSM_X4(b[2*i4][0], b[2*i4][1], b[2*i4+1][0], b[2*i4+1][1],
                        stb + boff[i4] + kb);
#pragma unroll
            for (int mt = 0; mt < 2; mt++)
#pragma unroll
                for (int nt = 0; nt < 8; nt++)
                    MMA_TF32(acc[mt][nt][0], acc[mt][nt][1], acc[mt][nt][2], acc[mt][nt][3],
                             a[mt][0], a[mt][1], a[mt][2], a[mt][3],
                             b[nt][0], b[nt][1]);
        }

        asm volatile("cp.async.wait_group 1;" ::: "memory");
        __syncthreads();
    }

#pragma unroll
    for (int mt = 0; mt < 2; mt++) {
#pragma unroll
        for (int nt = 0; nt < 8; nt++) {
            float v0 = acc[mt][nt][0], v1 = acc[mt][nt][1];
            float v2 = acc[mt][nt][2], v3 = acc[mt][nt][3];
            int col = n0 + warp_n + nt*8 + 2*tg;
            int r0 = m0 + warp_m + mt*16 + gid, r1 = r0 + 8;
            if (mode == 1) {
                *(float2*)(Cout + (size_t)r0*NDM + col) = make_float2(v0, v1);
                *(float2*)(Cout + (size_t)r1*NDM + col) = make_float2(v2, v3);
            } else {
                int h = col >> 6, d0 = col & 63;
                int b0i = r0 >> 11, l0 = r0 & (NL-1);
                int b1i = r1 >> 11, l1 = r1 & (NL-1);
                if (mat != 2) { v0=rna_tf32(v0); v1=rna_tf32(v1); v2=rna_tf32(v2); v3=rna_tf32(v3); }
                if (mat == 3) {   // kr transposed [bh][d][l]
                    float* base = g_proj[3];
                    base[((size_t)((b0i*NH+h)*ND + d0  ))*NL + l0] = v0;
                    base[((size_t)((b0i*NH+h)*ND + d0+1))*NL + l0] = v1;
                    base[((size_t)((b1i*NH+h)*ND + d0  ))*NL + l1] = v2;
                    base[((size_t)((b1i*NH+h)*ND + d0+1))*NL + l1] = v3;
                } else {
                    float* base = g_proj[mat];
                    *(float2*)(base + (((size_t)(b0i*NH+h))*NL + l0)*ND + d0) = make_float2(v0, v1);
                    *(float2*)(base + (((size_t)(b1i*NH+h))*NL + l1)*ND + d0) = make_float2(v2, v3);
                }
            }
        }
    }
}

// ---------------------------------------------------------------------------
// Flash attention on tensor cores; fragment loads via ldmatrix.
// K tiles natural [key][d]; Kr tiles from transposed buffer [d][key window].
// smem = 4 x (64*68) floats = 69632 B -> 3 CTAs/SM.
// ---------------------------------------------------------------------------
#define FSTR 68
#define KT_FLOATS (64*FSTR)          // 4352
#define KT_BYTES (KT_FLOATS*4)       // 17408

__global__ __launch_bounds__(128, 3) void flash_mma()
{
    extern __shared__ float fs[];
    float* sKt = fs;                           // 2 x [64][68]  K natural [key][d]
    float* sQ  = fs + KT_FLOATS;               // overlaps Kt stage 1
    float* sKr = fs + 2*KT_FLOATS;             // 2 x [64][68]  Kr^T [d][key]
    const uint32_t sKtb = smem_u32(sKt);
    const uint32_t sQb  = smem_u32(sQ);
    const uint32_t sKrb = smem_u32(sKr);

    const int qt = (int)(gridDim.x - 1 - blockIdx.x);   // heavy tiles first
    const int bh = blockIdx.y;
    const float* qp   = g_proj[0] + (size_t)bh*NL*ND;
    const float* kp   = g_proj[1] + (size_t)bh*NL*ND;   // natural [l][d]
    const float* qrp  = g_proj[2] + (size_t)bh*NL*ND;
    const float* krtp = g_proj[3] + (size_t)bh*ND*NL;   // transposed [d][l]

    const int t = threadIdx.x;
    const int wid = t >> 5, lane = t & 31;
    const int gid = lane >> 2, tg = lane & 3;
    const int g8 = lane >> 3, lr = lane & 7;
    const int wm = wid * 16;
    const int quad = lane & ~3;
    const int s_lo = quad + (tg >> 1);
    const int s_hi = s_lo + 2;
    const bool hi_slot = (tg & 1);

    // LDSM per-thread offsets (same pattern for Kt and Kr tiles)
    uint32_t foff[4];
#pragma unroll
    for (int i = 0; i < 4; i++)
        foff[i] = (uint32_t)((((i*2 + (g8>>1))*8 + lr)*FSTR + (g8&1)*4) * 4);

    // --- prologue: Q tile (into Kt stage-1 area) + j=0 K/Kr tiles (stage 0) ---
#pragma unroll
    for (int i = 0; i < 8; i++) {
        int idx = t + i*128;
        int row = idx >> 4, seg = idx & 15;
        asm volatile("cp.async.cg.shared.global [%0], [%1], 16;"
                     :: "r"(sQb + (uint32_t)(row*FSTR + seg*4)*4u),
                        "l"(qp + (size_t)(qt*64 + row)*ND + seg*4));
    }
#pragma unroll
    for (int i = 0; i < 8; i++) {
        int idx = t + i*128;
        int row = idx >> 4, seg = idx & 15;
        asm volatile("cp.async.cg.shared.global [%0], [%1], 16;"
                     :: "r"(sKtb + (uint32_t)(row*FSTR + seg*4)*4u),
                        "l"(kp + (size_t)row*ND + seg*4));
        asm volatile("cp.async.cg.shared.global [%0], [%1], 16;"
                     :: "r"(sKrb + (uint32_t)(row*FSTR + seg*4)*4u),
                        "l"(krtp + (size_t)row*NL + seg*4));
    }
    asm volatile("cp.async.commit_group;" ::: "memory");
    asm volatile("cp.async.wait_group 0;" ::: "memory");
    __syncthreads();

    // Q fragments (resident in registers)
    uint32_t aq[8][4];
    {
        const uint32_t* cQ = (const uint32_t*)sQ;
        int r0 = wm + gid;
#pragma unroll
        for (int k8 = 0; k8 < 8; k8++) {
            aq[k8][0] = cQ[r0*FSTR + k8*8 + tg];
            aq[k8][1] = cQ[(r0+8)*FSTR + k8*8 + tg];
            aq[k8][2] = cQ[r0*FSTR + k8*8 + tg + 4];
            aq[k8][3] = cQ[(r0+8)*FSTR + k8*8 + tg + 4];
        }
    }
    __syncthreads();   // Q reads done before stage-1 prefetch may overwrite

    float O[8][4];
#pragma unroll
    for (int q = 0; q < 8; q++) { O[q][0]=0.f; O[q][1]=0.f; O[q][2]=0.f; O[q][3]=0.f; }
    float m0v = -1e30f, m1v = -1e30f, l0v = 0.f, l1v = 0.f;

    const int row0 = qt*64 + wm + gid;
    const int row1 = row0 + 8;
    const float CEXP = 0.125f * 1.4426950408889634f;   // scale * log2(e)

    for (int j = 0; j <= qt; j++) {
        const int s = j & 1;
        if (j < qt) {
            const int sn = s ^ 1;
#pragma unroll
            for (int i = 0; i < 8; i++) {
                int idx = t + i*128;
                int row = idx >> 4, seg = idx & 15;
                asm volatile("cp.async.cg.shared.global [%0], [%1], 16;"
                             :: "r"(sKtb + (uint32_t)(sn*KT_FLOATS + row*FSTR + seg*4)*4u),
                                "l"(kp + (size_t)((j+1)*64 + row)*ND + seg*4));
                asm volatile("cp.async.cg.shared.global [%0], [%1], 16;"
                             :: "r"(sKrb + (uint32_t)(sn*KT_FLOATS + row*FSTR + seg*4)*4u),
                                "l"(krtp + (size_t)row*NL + (j+1)*64 + seg*4));
            }
            asm volatile("cp.async.commit_group;" ::: "memory");
        }

        // ---- S = Q @ K^T (B frags via LDSM on natural K tile) ----
        float sc[8][4];
#pragma unroll
        for (int q = 0; q < 8; q++) { sc[q][0]=0.f; sc[q][1]=0.f; sc[q][2]=0.f; sc[q][3]=0.f; }
        {
            const uint32_t ktb = sKtb + (uint32_t)(s * KT_BYTES);
#pragma unroll
            for (int k8 = 0; k8 < 8; k8++) {
                const uint32_t kb = (uint32_t)k8 * 32u;
                uint32_t b[8][2];
#pragma unroll
                for (int i4 = 0; i4 < 4; i4++)
                    LDSM_X4(b[2*i4][0], b[2*i4][1], b[2*i4+1][0], b[2*i4+1][1],
                            ktb + foff[i4] + kb);
#pragma unroll
                for (int q = 0; q < 8; q++)
                    MMA_TF32(sc[q][0], sc[q][1], sc[q][2], sc[q][3],
                             aq[k8][0], aq[k8][1], aq[k8][2], aq[k8][3],
                             b[q][0], b[q][1]);
            }
        }

        // ---- mask (raw scores) ----
        const bool diag = (j == qt);
        if (diag) {
#pragma unroll
            for (int q = 0; q < 8; q++) {
                int c0 = j*64 + q*8 + 2*tg, c1 = c0 + 1;
                if (c0 > row0) sc[q][0] = -1e30f;
                if (c1 > row0) sc[q][1] = -1e30f;
                if (c0 > row1) sc[q][2] = -1e30f;
                if (c1 > row1) sc[q][3] = -1e30f;
            }
        }

        // ---- online softmax (exp2-based; m in raw-score units) ----
        float mx0 = sc[0][0], mx1 = sc[0][2];
#pragma unroll
        for (int q = 0; q < 8; q++) {
            mx0 = fmaxf(mx0, fmaxf(sc[q][0], sc[q][1]));
            mx1 = fmaxf(mx1, fmaxf(sc[q][2], sc[q][3]));
        }
        mx0 = fmaxf(mx0, __shfl_xor_sync(0xffffffffu, mx0, 1));
        mx0 = fmaxf(mx0, __shfl_xor_sync(0xffffffffu, mx0, 2));
        mx1 = fmaxf(mx1, __shfl_xor_sync(0xffffffffu, mx1, 1));
        mx1 = fmaxf(mx1, __shfl_xor_sync(0xffffffffu, mx1, 2));
        float mn0 = fmaxf(m0v, mx0), mn1 = fmaxf(m1v, mx1);
        float cr0 = exp2f((m0v - mn0)*CEXP), cr1 = exp2f((m1v - mn1)*CEXP);
        m0v = mn0; m1v = mn1;
        const float b0 = mn0*CEXP, b1 = mn1*CEXP;

        float ps0 = 0.f, ps1 = 0.f;
#pragma unroll
        for (int q = 0; q < 8; q++) {
            sc[q][0] = exp2f(fmaf(sc[q][0], CEXP, -b0)); ps0 += sc[q][0];
            sc[q][1] = exp2f(fmaf(sc[q][1], CEXP, -b0)); ps0 += sc[q][1];
            sc[q][2] = exp2f(fmaf(sc[q][2], CEXP, -b1)); ps1 += sc[q][2];
            sc[q][3] = exp2f(fmaf(sc[q][3], CEXP, -b1)); ps1 += sc[q][3];
        }
        ps0 += __shfl_xor_sync(0xffffffffu, ps0, 1);
        ps0 += __shfl_xor_sync(0xffffffffu, ps0, 2);
        ps1 += __shfl_xor_sync(0xffffffffu, ps1, 1);
        ps1 += __shfl_xor_sync(0xffffffffu, ps1, 2);
        l0v = l0v*cr0 + ps0;
        l1v = l1v*cr1 + ps1;

#pragma unroll
        for (int q = 0; q < 8; q++) {
            O[q][0] *= cr0; O[q][1] *= cr0; O[q][2] *= cr1; O[q][3] *= cr1;
        }

        // ---- P accumulator layout -> A fragment layout (quad shuffles) ----
        uint32_t pa[8][4];
#pragma unroll
        for (int q = 0; q < 8; q++) {
            float p0 = rna_tf32(sc[q][0]), p1 = rna_tf32(sc[q][1]);
            float p2 = rna_tf32(sc[q][2]), p3 = rna_tf32(sc[q][3]);
            float t00 = __shfl_sync(0xffffffffu, p0, s_lo);
            float t01 = __shfl_sync(0xffffffffu, p1, s_lo);
            float t20 = __shfl_sync(0xffffffffu, p2, s_lo);
            float t21 = __shfl_sync(0xffffffffu, p3, s_lo);
            float t02 = __shfl_sync(0xffffffffu, p0, s_hi);
            float t12 = __shfl_sync(0xffffffffu, p1, s_hi);
            float t22 = __shfl_sync(0xffffffffu, p2, s_hi);
            float t32 = __shfl_sync(0xffffffffu, p3, s_hi);
            pa[q][0] = __float_as_uint(hi_slot ? t01 : t00);
            pa[q][1] = __float_as_uint(hi_slot ? t21 : t20);
            pa[q][2] = __float_as_uint(hi_slot ? t12 : t02);
            pa[q][3] = __float_as_uint(hi_slot ? t32 : t22);
        }

        // ---- O += P @ Kr (B frags via LDSM on Kr^T tile) ----
        {
            const uint32_t krb = sKrb + (uint32_t)(s * KT_BYTES);
#pragma unroll
            for (int k8 = 0; k8 < 8; k8++) {
                const uint32_t kb = (uint32_t)k8 * 32u;
                uint32_t b[8][2];
#pragma unroll
                for (int i4 = 0; i4 < 4; i4++)
                    LDSM_X4(b[2*i4][0], b[2*i4][1], b[2*i4+1][0], b[2*i4+1][1],
                            krb + foff[i4] + kb);
#pragma unroll
                for (int nt = 0; nt < 8; nt++)
                    MMA_TF32(O[nt][0], O[nt][1], O[nt][2], O[nt][3],
                             pa[k8][0], pa[k8][1], pa[k8][2], pa[k8][3],
                             b[nt][0], b[nt][1]);
            }
        }

        if (j < qt) {
            asm volatile("cp.async.wait_group 0;" ::: "memory");
            __syncthreads();
        }
    }

    // ---- epilogue ----
    const float inv0 = 1.f / l0v, inv1 = 1.f / l1v;
    const int b = bh >> 4, h = bh & 15;
    const int li0 = row0, li1 = row1;
    float* out0 = g_att + ((size_t)(b*NL + li0))*NDM + h*64;
    float* out1 = g_att + ((size_t)(b*NL + li1))*NDM + h*64;
#pragma unroll
    for (int q = 0; q < 8; q++) {
        int d = q*8 + 2*tg;
        float2 qr0 = *(const float2*)(qrp + (size_t)li0*ND + d);
        float2 qr1 = *(const float2*)(qrp + (size_t)li1*ND + d);
        float2 o0, o1;
        o0.x = rna_tf32(O[q][0]*inv0*qr0.x); o0.y = rna_tf32(O[q][1]*inv0*qr0.y);
        o1.x = rna_tf32(O[q][2]*inv1*qr1.x); o1.y = rna_tf32(O[q][3]*inv1*qr1.y);
        *(float2*)(out0 + d) = o0;
        *(float2*)(out1 + d) = o1;
    }
}

// ---------------------------------------------------------------------------
extern "C" void kernel_launch(void* const* d_in, const int* in_sizes, int n_in,
                              void* d_out, int out_size)
{
    const float* x   = (const float*)d_in[0];
    const float* wq  = (const float*)d_in[1];
    const float* wk  = (const float*)d_in[2];
    const float* wqr = (const float*)d_in[3];
    const float* wkr = (const float*)d_in[4];
    const float* wo  = (const float*)d_in[5];
    float* out = (float*)d_out;

    round_x<<<4096, 256>>>((const float4*)x);
    wtrans<<<dim3(32, 32, 5), 256>>>(wq, wk, wqr, wkr, wo);

    const int gsmem = 3 * STG_FLOATS * (int)sizeof(float);   // 110592
    cudaFuncSetAttribute(gemm_tc, cudaFuncAttributeMaxDynamicSharedMemorySize, gsmem);
    gemm_tc<<<dim3(NDM/BN, NM/BM, 4), 256, gsmem>>>(out, 0);

    const int fsmem = 4 * KT_FLOATS * (int)sizeof(float);    // 69632
    cudaFuncSetAttribute(flash_mma, cudaFuncAttributeMaxDynamicSharedMemorySize, fsmem);
    flash_mma<<<dim3(NL/64, NB*NH), 128, fsmem>>>();

    gemm_tc<<<dim3(NDM/BN, NM/BM, 1), 256, gsmem>>>(out, 1);
}